// round 15
// baseline (speedup 1.0000x reference)
#include <cuda_runtime.h>
#include <cuda_bf16.h>
#include <math.h>
#include <stdint.h>

#define NWIN 256
#define NTOK 294
#define NHEAD 8
#define DHD 32
#define DIM 256
#define MROWS (NWIN*NTOK)        // 75264
#define NPAIR (NTOK*NTOK)        // 86436
#define QSCALE 0.17677669529663687f  // 32^-0.5

// ---------------- scratch ----------------------------------------------------
__device__ float g_biasT[(size_t)NHEAD*NPAIR];
__device__ __nv_bfloat16 g_ah[(size_t)MROWS*DIM];
__device__ __nv_bfloat16 g_al[(size_t)MROWS*DIM];
__device__ __nv_bfloat16 g_qh[(size_t)MROWS*DIM];
__device__ __nv_bfloat16 g_ql[(size_t)MROWS*DIM];
__device__ __nv_bfloat16 g_kh2[(size_t)MROWS*DIM];
__device__ __nv_bfloat16 g_kl2[(size_t)MROWS*DIM];
__device__ __nv_bfloat16 g_vh[(size_t)MROWS*DIM];
__device__ __nv_bfloat16 g_vl[(size_t)MROWS*DIM];
__device__ __nv_bfloat16 g_aoh[(size_t)MROWS*DIM];
__device__ __nv_bfloat16 g_aol[(size_t)MROWS*DIM];
__device__ __nv_bfloat16 g_bhq[768*256];
__device__ __nv_bfloat16 g_blq[768*256];
__device__ __nv_bfloat16 g_bho[256*256];
__device__ __nv_bfloat16 g_blo[256*256];

// ---------------- helpers -----------------------------------------------------
__device__ __forceinline__ uint32_t smem_u32(const void* p) {
    return (uint32_t)__cvta_generic_to_shared(p);
}
__device__ __forceinline__ void ldsm_x4(uint32_t& r0, uint32_t& r1,
                                        uint32_t& r2, uint32_t& r3, uint32_t a) {
    asm volatile("ldmatrix.sync.aligned.m8n8.x4.shared.b16 {%0,%1,%2,%3}, [%4];"
                 : "=r"(r0), "=r"(r1), "=r"(r2), "=r"(r3) : "r"(a));
}
__device__ __forceinline__ void mma_bf16(float* c, uint32_t a0, uint32_t a1,
                                         uint32_t a2, uint32_t a3,
                                         uint32_t b0, uint32_t b1) {
    asm volatile(
        "mma.sync.aligned.m16n8k16.row.col.f32.bf16.bf16.f32 "
        "{%0,%1,%2,%3}, {%4,%5,%6,%7}, {%8,%9}, {%0,%1,%2,%3};"
        : "+f"(c[0]), "+f"(c[1]), "+f"(c[2]), "+f"(c[3])
        : "r"(a0), "r"(a1), "r"(a2), "r"(a3), "r"(b0), "r"(b1));
}
__device__ __forceinline__ uint32_t cvt_bf2(float a, float b) {
    uint32_t r;
    asm("cvt.rn.bf16x2.f32 %0, %1, %2;" : "=r"(r) : "f"(b), "f"(a));
    return r;
}
__device__ __forceinline__ float bf_lo(uint32_t r) { return __uint_as_float(r << 16); }
__device__ __forceinline__ float bf_hi(uint32_t r) { return __uint_as_float(r & 0xffff0000u); }
__device__ __forceinline__ void cpa16(uint32_t s, const void* g) {
    asm volatile("cp.async.cg.shared.global [%0], [%1], 16;" :: "r"(s), "l"(g));
}
#define CPA_COMMIT() asm volatile("cp.async.commit_group;" ::: "memory")
#define CPA_WAIT0()  asm volatile("cp.async.wait_group 0;" ::: "memory")
#define CPA_WAIT1()  asm volatile("cp.async.wait_group 1;" ::: "memory")

// swizzled 16B-chunk offset inside a [rows][4 chunks] (64B-row) tile.
__device__ __forceinline__ uint32_t sw_off(int r, int c) {
    return (uint32_t)(r*64 + ((c ^ ((r >> 1) & 3)) << 4));
}
// Vt tile: 32 rows x 640B (40 chunks of 16B), conflict-free xor swizzle
__device__ __forceinline__ uint32_t vt_off(int d, int c) {
    return (uint32_t)(d*640 + ((((c) & ~7) | (((c) & 7) ^ (d & 7))) << 4));
}
// fp32 epilogue tile: 128 rows x 512B; 8B-unit xor swizzle (conflict-free)
__device__ __forceinline__ uint32_t ep32_off(int r, int cw) {
    return (uint32_t)(r*512 + ((cw ^ ((r & 7) << 2)) << 3));
}

// GEMM row (window-major) -> x/out row (l-major)
__device__ __forceinline__ int map_row(int r) {
    int win = r / NTOK;
    int tok = r - win*NTOK;
    int l   = tok / 49;
    int ww  = tok - l*49;
    return l*12544 + win*49 + ww;
}

// ---------------- merged prelude kernel -----------------------------------------
#define PREP_XS 9408
#define PREP_WQ (PREP_XS + 768)
#define PREP_WO (PREP_WQ + 256)
#define PREP_TOT (PREP_WO + 338)

__global__ void prep_kernel(const float* __restrict__ X,
                            const float* __restrict__ WQ,
                            const float* __restrict__ WO,
                            const int* __restrict__ rel,
                            const float* __restrict__ table,
                            __nv_bfloat16* __restrict__ AH,
                            __nv_bfloat16* __restrict__ AL,
                            __nv_bfloat16* __restrict__ BHQ,
                            __nv_bfloat16* __restrict__ BLQ,
                            __nv_bfloat16* __restrict__ BHO,
                            __nv_bfloat16* __restrict__ BLO,
                            float* __restrict__ biasT) {
    int b = blockIdx.x;
    int tid = threadIdx.x;
    if (b < PREP_XS) {
        int i = b*256 + tid;
        int r = i >> 5, c8 = i & 31;
        const float* src = X + (size_t)map_row(r)*DIM + c8*8;
        float4 f0 = *(const float4*)src;
        float4 f1 = *(const float4*)(src + 4);
        float buf[8] = {f0.x, f0.y, f0.z, f0.w, f1.x, f1.y, f1.z, f1.w};
        __nv_bfloat16 h[8], l[8];
        #pragma unroll
        for (int e = 0; e < 8; e++) {
            __nv_bfloat16 hi = __float2bfloat16(buf[e]);
            h[e] = hi;
            l[e] = __float2bfloat16(buf[e] - __bfloat162float(hi));
        }
        *(uint4*)(AH + (size_t)r*DIM + c8*8) = *(uint4*)h;
        *(uint4*)(AL + (size_t)r*DIM + c8*8) = *(uint4*)l;
    } else if (b < PREP_WQ) {
        int i = (b - PREP_XS)*256 + tid;
        int n = i >> 8, k = i & 255;
        float x = WQ[(size_t)k*768 + n];
        if (n < 256) x *= QSCALE;                  // fold q-scale into weights
        __nv_bfloat16 hi = __float2bfloat16(x);
        BHQ[(size_t)n*256 + k] = hi;
        BLQ[(size_t)n*256 + k] = __float2bfloat16(x - __bfloat162float(hi));
    } else if (b < PREP_WO) {
        int i = (b - PREP_WQ)*256 + tid;
        int n = i >> 8, k = i & 255;
        float x = WO[(size_t)k*256 + n];
        __nv_bfloat16 hi = __float2bfloat16(x);
        BHO[(size_t)n*256 + k] = hi;
        BLO[(size_t)n*256 + k] = __float2bfloat16(x - __bfloat162float(hi));
    } else {
        int t = (b - PREP_WO)*256 + tid;
        if (t >= NPAIR) return;
        int j = t / NTOK, i = t - j*NTOK;
        int idx = rel[i*NTOK + j];
        #pragma unroll
        for (int h = 0; h < NHEAD; h++)
            biasT[(size_t)h*NPAIR + t] = table[idx*NHEAD + h];
    }
}

// ---------------- 3-stage cp.async mma.sync GEMM --------------------------------
#define G_STAGE 32768
#define G_SMEM  (3*G_STAGE)
#define EP_STRIDE 272   /* bf16 epilogue row stride */

template<bool QKV>
__device__ __forceinline__ void gemm2_body(
        const __nv_bfloat16* __restrict__ AHg, const __nv_bfloat16* __restrict__ ALg,
        const __nv_bfloat16* __restrict__ BHg, const __nv_bfloat16* __restrict__ BLg,
        __nv_bfloat16* QH, __nv_bfloat16* QL,
        __nv_bfloat16* KH, __nv_bfloat16* KL,
        __nv_bfloat16* VH, __nv_bfloat16* VL,
        float* __restrict__ OUT, int yoff) {
    extern __shared__ __align__(16) uint8_t dsm[];
    uint32_t sb = smem_u32(dsm);
    int tid  = threadIdx.x;
    int lane = tid & 31;
    int wid  = tid >> 5;
    int wm   = wid & 1;
    int wn   = wid >> 1;
    int m0 = (blockIdx.y + yoff) * 128;
    int n0 = blockIdx.x * 128;

    int r0 = tid >> 2, c0 = tid & 3;
    const __nv_bfloat16* gAH0 = AHg + (size_t)(m0 + r0)*256      + c0*8;
    const __nv_bfloat16* gAH1 = AHg + (size_t)(m0 + r0 + 64)*256 + c0*8;
    const __nv_bfloat16* gAL0 = ALg + (size_t)(m0 + r0)*256      + c0*8;
    const __nv_bfloat16* gAL1 = ALg + (size_t)(m0 + r0 + 64)*256 + c0*8;
    const __nv_bfloat16* gBH0 = BHg + (size_t)(n0 + r0)*256      + c0*8;
    const __nv_bfloat16* gBH1 = BHg + (size_t)(n0 + r0 + 64)*256 + c0*8;
    const __nv_bfloat16* gBL0 = BLg + (size_t)(n0 + r0)*256      + c0*8;
    const __nv_bfloat16* gBL1 = BLg + (size_t)(n0 + r0 + 64)*256 + c0*8;
    uint32_t oA0 = sw_off(r0, c0), oA1 = sw_off(r0 + 64, c0);

#define STAGE_LOAD(ST, KT) do {                                   \
        uint32_t _b = sb + (ST)*G_STAGE;                          \
        cpa16(_b + 0     + oA0, gAH0 + (KT));                     \
        cpa16(_b + 0     + oA1, gAH1 + (KT));                     \
        cpa16(_b + 8192  + oA0, gAL0 + (KT));                     \
        cpa16(_b + 8192  + oA1, gAL1 + (KT));                     \
        cpa16(_b + 16384 + oA0, gBH0 + (KT));                     \
        cpa16(_b + 16384 + oA1, gBH1 + (KT));                     \
        cpa16(_b + 24576 + oA0, gBL0 + (KT));                     \
        cpa16(_b + 24576 + oA1, gBL1 + (KT));                     \
        CPA_COMMIT();                                             \
    } while (0)

    int a_row = ((lane >> 3) & 1)*8 + (lane & 7);
    int a_ch  = lane >> 4;
    int b_row = (lane >> 4)*8 + (lane & 7);
    int b_ch  = (lane >> 3) & 1;

    float acc[4][4][4];
    #pragma unroll
    for (int i = 0; i < 4; i++)
        #pragma unroll
        for (int j = 0; j < 4; j++)
            #pragma unroll
            for (int e = 0; e < 4; e++) acc[i][j][e] = 0.f;

    STAGE_LOAD(0, 0);
    STAGE_LOAD(1, 32);

    #pragma unroll
    for (int kt8 = 0; kt8 < 8; kt8++) {
        if (kt8 < 7) CPA_WAIT1(); else CPA_WAIT0();
        __syncthreads();
        if (kt8 + 2 < 8) STAGE_LOAD((kt8 + 2) % 3, (kt8 + 2)*32);

        uint32_t ah_b = sb + (kt8 % 3)*G_STAGE;
        uint32_t al_b = ah_b + 8192;
        uint32_t bh_b = ah_b + 16384;
        uint32_t bl_b = ah_b + 24576;

        #pragma unroll
        for (int s = 0; s < 2; s++) {
            uint32_t ah[16], al[16], bh[8], bl[8];
            #pragma unroll
            for (int mf = 0; mf < 4; mf++) {
                uint32_t off = sw_off(wm*64 + mf*16 + a_row, s*2 + a_ch);
                ldsm_x4(ah[4*mf], ah[4*mf+1], ah[4*mf+2], ah[4*mf+3], ah_b + off);
                ldsm_x4(al[4*mf], al[4*mf+1], al[4*mf+2], al[4*mf+3], al_b + off);
            }
            #pragma unroll
            for (int np = 0; np < 2; np++) {
                uint32_t off = sw_off(wn*32 + np*16 + b_row, s*2 + b_ch);
                ldsm_x4(bh[4*np], bh[4*np+1], bh[4*np+2], bh[4*np+3], bh_b + off);
                ldsm_x4(bl[4*np], bl[4*np+1], bl[4*np+2], bl[4*np+3], bl_b + off);
            }
            #pragma unroll
            for (int mf = 0; mf < 4; mf++)
                #pragma unroll
                for (int nf = 0; nf < 4; nf++) {
                    mma_bf16(acc[mf][nf], ah[4*mf], ah[4*mf+1], ah[4*mf+2], ah[4*mf+3],
                             bh[2*nf], bh[2*nf+1]);
                    mma_bf16(acc[mf][nf], ah[4*mf], ah[4*mf+1], ah[4*mf+2], ah[4*mf+3],
                             bl[2*nf], bl[2*nf+1]);
                    mma_bf16(acc[mf][nf], al[4*mf], al[4*mf+1], al[4*mf+2], al[4*mf+3],
                             bh[2*nf], bh[2*nf+1]);
                }
        }
    }

    int tq = lane >> 2;
    int tr = (lane & 3)*2;
    if (QKV) {
        int sel = n0 >> 8;
        int cc0 = n0 & 255;
        __nv_bfloat16* dh = (sel == 0) ? QH : (sel == 1) ? KH : VH;
        __nv_bfloat16* dl = (sel == 0) ? QL : (sel == 1) ? KL : VL;
        #pragma unroll
        for (int pl = 0; pl < 2; pl++) {
            __syncthreads();
            #pragma unroll
            for (int mf = 0; mf < 4; mf++)
                #pragma unroll
                for (int nf = 0; nf < 4; nf++) {
                    int r = wm*64 + mf*16 + tq;
                    int cb = (wn*32 + nf*8 + tr)*2;
                    float v0 = acc[mf][nf][0], v1 = acc[mf][nf][1];
                    float v2 = acc[mf][nf][2], v3 = acc[mf][nf][3];
                    uint32_t h0 = cvt_bf2(v0, v1);
                    uint32_t h1 = cvt_bf2(v2, v3);
                    uint32_t w0, w1;
                    if (pl == 0) { w0 = h0; w1 = h1; }
                    else {
                        w0 = cvt_bf2(v0 - bf_lo(h0), v1 - bf_hi(h0));
                        w1 = cvt_bf2(v2 - bf_lo(h1), v3 - bf_hi(h1));
                    }
                    *(uint32_t*)(dsm + r*EP_STRIDE + cb)       = w0;
                    *(uint32_t*)(dsm + (r + 8)*EP_STRIDE + cb) = w1;
                }
            __syncthreads();
            __nv_bfloat16* dst = (pl == 0) ? dh : dl;
            #pragma unroll
            for (int k2 = 0; k2 < 8; k2++) {
                int idx = tid + k2*256;
                int r = idx >> 4, ch = idx & 15;
                uint4 val = *(uint4*)(dsm + r*EP_STRIDE + ch*16);
                *(uint4*)(dst + (size_t)(m0 + r)*256 + cc0 + ch*8) = val;
            }
        }
    } else {
        __syncthreads();
        #pragma unroll
        for (int mf = 0; mf < 4; mf++)
            #pragma unroll
            for (int nf = 0; nf < 4; nf++) {
                int r = wm*64 + mf*16 + tq;
                int cw = (wn*32 + nf*8 + tr) >> 1;
                float2 v0 = {acc[mf][nf][0], acc[mf][nf][1]};
                float2 v1 = {acc[mf][nf][2], acc[mf][nf][3]};
                *(float2*)(dsm + ep32_off(r, cw))     = v0;
                *(float2*)(dsm + ep32_off(r + 8, cw)) = v1;
            }
        __syncthreads();
        #pragma unroll
        for (int k2 = 0; k2 < 16; k2++) {
            int idx = tid + k2*256;
            int r = idx >> 5, ch = idx & 31;
            uint4 val = *(uint4*)(dsm + ep32_off(r, 2*ch));
            int g = map_row(m0 + r);
            *(uint4*)(OUT + (size_t)g*256 + n0 + ch*4) = val;
        }
    }
#undef STAGE_LOAD
}

__global__ __launch_bounds__(256, 2) void qkv_mma_kernel(
        const __nv_bfloat16* __restrict__ AH, const __nv_bfloat16* __restrict__ AL,
        const __nv_bfloat16* __restrict__ BH, const __nv_bfloat16* __restrict__ BL,
        __nv_bfloat16* QH, __nv_bfloat16* QL, __nv_bfloat16* KH, __nv_bfloat16* KL,
        __nv_bfloat16* VH, __nv_bfloat16* VL, int yoff) {
    gemm2_body<true>(AH, AL, BH, BL, QH, QL, KH, KL, VH, VL, nullptr, yoff);
}

__global__ __launch_bounds__(256, 2) void proj_mma_kernel(
        const __nv_bfloat16* __restrict__ AH, const __nv_bfloat16* __restrict__ AL,
        const __nv_bfloat16* __restrict__ BH, const __nv_bfloat16* __restrict__ BL,
        float* __restrict__ OUT, int yoff) {
    gemm2_body<false>(AH, AL, BH, BL,
                      nullptr, nullptr, nullptr, nullptr, nullptr, nullptr, OUT, yoff);
}

// ---------------- attention via mma.sync + cp.async staging ----------------------
#define MPAD 320
#define A_QH 0
#define A_QL 20480
#define A_KH 40960
#define A_KL 60416
#define A_VTH 79872
#define A_VTL 100352
#define A_MSKF 120832
#define A_KLIST 122048
#define A_MSRAW 123264
#define A_PCNT 124448
#define A_SMEM 124464

__global__ __launch_bounds__(320, 1) void attn_mma_kernel(
        const __nv_bfloat16* __restrict__ gqh, const __nv_bfloat16* __restrict__ gql,
        const __nv_bfloat16* __restrict__ gkh, const __nv_bfloat16* __restrict__ gkl,
        const __nv_bfloat16* __restrict__ gvh, const __nv_bfloat16* __restrict__ gvl,
        const int* __restrict__ mask, const float* __restrict__ biasT,
        __nv_bfloat16* __restrict__ aoh, __nv_bfloat16* __restrict__ aol,
        int win_base) {
    extern __shared__ __align__(16) uint8_t sm8[];
    float* mskf = (float*)(sm8 + A_MSKF);
    int*   kls  = (int*)(sm8 + A_KLIST);
    int*   msr  = (int*)(sm8 + A_MSRAW);
    int*   pcnt = (int*)(sm8 + A_PCNT);

    int tid = threadIdx.x, lane = tid & 31, wid = tid >> 5;
    // head-major ordering within the half: concurrent CTAs share one head's bias
    int h   = blockIdx.x >> 7;
    int win = (blockIdx.x & 127) + win_base;
    size_t base = ((size_t)win*NTOK)*DIM + h*DHD;
    uint32_t sb = smem_u32(sm8);

    for (int idx = tid; idx < NTOK*4; idx += 320) {
        int r = idx >> 2, c = idx & 3;
        size_t src = base + (size_t)r*DIM + c*8;
        uint32_t off = sw_off(r, c);
        cpa16(sb + A_QH + off, gqh + src);
        cpa16(sb + A_QL + off, gql + src);
    }
    for (int t = tid; t < NTOK; t += 320) {
        int l = t / 49, ww = t - l*49;
        msr[t] = mask[(win*49 + ww)*6 + l];
    }
    for (int t = tid; t < 304; t += 320) { kls[t] = 293; mskf[t] = 0.f; }
    for (int idx = NTOK*4 + tid; idx < MPAD*4; idx += 320) {
        int r = idx >> 2, c = idx & 3;
        uint4 z = {0, 0, 0, 0};
        uint32_t off = sw_off(r, c);
        *(uint4*)(sm8 + A_QH + off) = z;
        *(uint4*)(sm8 + A_QL + off) = z;
    }
    __syncthreads();

    if (tid < 32) {
        int c = 0;
        for (int b0 = 0; b0 < NTOK; b0 += 32) {
            int j = b0 + lane;
            int mj = (j < NTOK) ? msr[j] : 0;
            unsigned bal = __ballot_sync(0xffffffffu, mj != 0);
            if (mj) {
                int pos = c + __popc(bal & ((1u << lane) - 1));
                kls[pos] = j;
                mskf[pos] = 1.f;
            }
            c += __popc(bal);
        }
        if (lane == 0) pcnt[0] = c;
    }
    __syncthreads();
    int cnt  = pcnt[0];
    int nch  = (cnt + 15) >> 4;
    int cntp = nch << 4;

    for (int idx = tid; idx < cntp*4; idx += 320) {
        int jj = idx >> 2, c = idx & 3;
        int j = kls[jj];
        size_t src = base + (size_t)j*DIM + c*8;
        uint32_t off = sw_off(jj, c);
        cpa16(sb + A_KH + off, gkh + src);
        cpa16(sb + A_KL + off, gkl + src);
    }
    for (int idx = tid; idx < cntp*4; idx += 320) {
        int jp = idx >> 3, d4 = idx & 7;
        int jj0 = jp*2;
        int j0 = kls[jj0], j1 = kls[jj0 + 1];
        size_t s0 = base + (size_t)j0*DIM + d4*4;
        size_t s1 = base + (size_t)j1*DIM + d4*4;
        uint2 wh0 = *(const uint2*)(gvh + s0);
        uint2 wh1 = *(const uint2*)(gvh + s1);
        uint2 wl0 = *(const uint2*)(gvl + s0);
        uint2 wl1 = *(const uint2*)(gvl + s1);
        int cb = jj0 >> 3;
        int ib = (jj0 & 7)*2;
        int d = d4*4;
        *(uint32_t*)(sm8 + A_VTH + vt_off(d+0, cb) + ib) = __byte_perm(wh0.x, wh1.x, 0x5410);
        *(uint32_t*)(sm8 + A_VTH + vt_off(d+1, cb) + ib) = __byte_perm(wh0.x, wh1.x, 0x7632);
        *(uint32_t*)(sm8 + A_VTH + vt_off(d+2, cb) + ib) = __byte_perm(wh0.y, wh1.y, 0x5410);
        *(uint32_t*)(sm8 + A_VTH + vt_off(d+3, cb) + ib) = __byte_perm(wh0.y, wh1.y, 0x7632);
        *(uint32_t*)(sm8 + A_VTL + vt_off(d+0, cb) + ib) = __byte_perm(wl0.x, wl1.x, 0x5410);
        *(uint32_t*)(sm8 + A_VTL + vt_off(d+1, cb) + ib) = __byte_perm(wl0.x, wl1.x, 0x7632);
        *(uint32_t*)(sm8 + A_VTL + vt_off(d+2, cb) + ib) = __byte_perm(wl0.y, wl1.y, 0x5410);
        *(uint32_t*)(sm8 + A_VTL + vt_off(d+3, cb) + ib) = __byte_perm(wl0.y, wl1.y, 0x7632);
    }
    CPA_COMMIT();
    CPA_WAIT0();
    __syncthreads();

    int tq = lane >> 2;
    int tr = (lane & 3)*2;
    int a_row = ((lane >> 3) & 1)*8 + (lane & 7);
    int a_ch  = lane >> 4;
    int b_row = (lane >> 4)*8 + (lane & 7);
    int b_ch  = (lane >> 3) & 1;
    int wm0 = wid*32;

    uint32_t qh[2][2][4], ql[2][2][4];
    #pragma unroll
    for (int mf = 0; mf < 2; mf++)
        #pragma unroll
        for (int s = 0; s < 2; s++) {
            uint32_t off = sw_off(wm0 + mf*16 + a_row, s*2 + a_ch);
            ldsm_x4(qh[mf][s][0], qh[mf][s][1], qh[mf][s][2], qh[mf][s][3], sb + A_QH + off);
            ldsm_x4(ql[mf][s][0], ql[mf][s][1], ql[mf][s][2], ql[mf][s][3], sb + A_QL + off);
        }

    int i0a[2], i1a[2];
    #pragma unroll
    for (int mf = 0; mf < 2; mf++) {
        int b0 = wm0 + mf*16 + tq;
        i0a[mf] = (b0 < 293) ? b0 : 293;
        int b1 = b0 + 8;
        i1a[mf] = (b1 < 293) ? b1 : 293;
    }
    const float* bp = biasT + (size_t)h*NPAIR;

    float oacc[2][4][4];
    #pragma unroll
    for (int mf = 0; mf < 2; mf++)
        #pragma unroll
        for (int nf = 0; nf < 4; nf++)
            #pragma unroll
            for (int e = 0; e < 4; e++) oacc[mf][nf][e] = 0.f;
    float rs[2][2] = {{0.f, 0.f}, {0.f, 0.f}};

    float bc[2][2][4], mc[2][2];
#define LOAD_BIAS(CH, B, M) do {                                            \
        int _kb = (CH)*16;                                                  \
        _Pragma("unroll")                                                   \
        for (int _nf = 0; _nf < 2; _nf++) {                                 \
            int2 _j2 = *(const int2*)(kls + _kb + _nf*8 + tr);              \
            float2 _m2 = *(const float2*)(mskf + _kb + _nf*8 + tr);         \
            (M)[_nf][0] = _m2.x; (M)[_nf][1] = _m2.y;                       \
            const float* _ba = bp + (size_t)_j2.x*NTOK;                     \
            const float* _bb = bp + (size_t)_j2.y*NTOK;                     \
            _Pragma("unroll")                                               \
            for (int _mf = 0; _mf < 2; _mf++) {                             \
                (B)[_mf][_nf][0] = __ldg(_ba + i0a[_mf]);                   \
                (B)[_mf][_nf][1] = __ldg(_bb + i0a[_mf]);                   \
                (B)[_mf][_nf][2] = __ldg(_ba + i1a[_mf]);                   \
                (B)[_mf][_nf][3] = __ldg(_bb + i1a[_mf]);                   \
            }                                                               \
        } } while (0)

    LOAD_BIAS(0, bc, mc);

    for (int ch = 0; ch < nch; ch++) {
        int kb = ch*16;
        uint32_t kh[8], kl2[8], vh[8], vl[8];
        {
            uint32_t o0 = sw_off(kb + b_row, b_ch);
            uint32_t o1 = sw_off(kb + b_row, 2 + b_ch);
            ldsm_x4(kh[0], kh[1], kh[2], kh[3], sb + A_KH + o0);
            ldsm_x4(kh[4], kh[5], kh[6], kh[7], sb + A_KH + o1);
            ldsm_x4(kl2[0], kl2[1], kl2[2], kl2[3], sb + A_KL + o0);
            ldsm_x4(kl2[4], kl2[5], kl2[6], kl2[7], sb + A_KL + o1);
            uint32_t v0o = vt_off(b_row, ch*2 + b_ch);
            uint32_t v1o = vt_off(16 + b_row, ch*2 + b_ch);
            ldsm_x4(vh[0], vh[1], vh[2], vh[3], sb + A_VTH + v0o);
            ldsm_x4(vh[4], vh[5], vh[6], vh[7], sb + A_VTH + v1o);
            ldsm_x4(vl[0], vl[1], vl[2], vl[3], sb + A_VTL + v0o);
            ldsm_x4(vl[4], vl[5], vl[6], vl[7], sb + A_VTL + v1o);
        }

        float bn[2][2][4], mn2[2][2];
        if (ch + 1 < nch) LOAD_BIAS(ch + 1, bn, mn2);

        float sacc[2][2][4];
        #pragma unroll
        for (int mf = 0; mf < 2; mf++)
            #pragma unroll
            for (int nf = 0; nf < 2; nf++)
                #pragma unroll
                for (int e = 0; e < 4; e++) sacc[mf][nf][e] = 0.f;

        #pragma unroll
        for (int mf = 0; mf < 2; mf++)
            #pragma unroll
            for (int s = 0; s < 2; s++) {
                mma_bf16(sacc[mf][0], qh[mf][s][0], qh[mf][s][1], qh[mf][s][2], qh[mf][s][3],
                         kh[4*s], kh[4*s+1]);
                mma_bf16(sacc[mf][1], qh[mf][s][0], qh[mf][s][1], qh[mf][s][2], qh[mf][s][3],
                         kh[4*s+2], kh[4*s+3]);
                mma_bf16(sacc[mf][0], qh[mf][s][0], qh[mf][s][1], qh[mf][s][2], qh[mf][s][3],
                         kl2[4*s], kl2[4*s+1]);
                mma_bf16(sacc[mf][1], qh[mf][s][0], qh[mf][s][1], qh[mf][s][2], qh[mf][s][3],
                         kl2[4*s+2], kl2[4*s+3]);
                mma_bf16(sacc[mf][0], ql[mf][s][0], ql[mf][s][1], ql[mf][s][2], ql[mf][s][3],
                         kh[4*s], kh[4*s+1]);
                mma_bf16(sacc[mf][1], ql[mf][s][0], ql[mf][s][1], ql[mf][s][2], ql[mf][s][3],
                         kh[4*s+2], kh[4*s+3]);
            }

        uint32_t pah[2][4], pal[2][4];
        #pragma unroll
        for (int mf = 0; mf < 2; mf++)
            #pragma unroll
            for (int nf = 0; nf < 2; nf++) {
                float p0 = __expf(sacc[mf][nf][0] + bc[mf][nf][0]) * mc[nf][0];
                float p1 = __expf(sacc[mf][nf][1] + bc[mf][nf][1]) * mc[nf][1];
                float p2 = __expf(sacc[mf][nf][2] + bc[mf][nf][2]) * mc[nf][0];
                float p3 = __expf(sacc[mf][nf][3] + bc[mf][nf][3]) * mc[nf][1];
                rs[mf][0] += p0 + p1;
                rs[mf][1] += p2 + p3;
                uint32_t hA = cvt_bf2(p0, p1);
                uint32_t hB = cvt_bf2(p2, p3);
                pah[mf][2*nf]   = hA;
                pah[mf][2*nf+1] = hB;
                pal[mf][2*nf]   = cvt_bf2(p0 - bf_lo(hA), p1 - bf_hi(hA));
                pal[mf][2*nf+1] = cvt_bf2(p2 - bf_lo(hB), p3 - bf_hi(hB));
            }

        #pragma unroll
        for (int mf = 0; mf < 2; mf++)
            #pragma unroll
            for (int nf4 = 0; nf4 < 4; nf4++) {
                mma_bf16(oacc[mf][nf4], pah[mf][0], pah[mf][1], pah[mf][2], pah[mf][3],
                         vh[2*nf4], vh[2*nf4+1]);
                mma_bf16(oacc[mf][nf4], pah[mf][0], pah[mf][1], pah[mf][2], pah[mf][3],
                         vl[2*nf4], vl[2*nf4+1]);
                mma_bf16(oacc[mf][nf4], pal[mf][0], pal[mf][1], pal[mf][2], pal[mf][3],
                         vh[2*nf4], vh[2*nf4+1]);
            }

        #pragma unroll
        for (int mf = 0; mf < 2; mf++)
            #pragma unroll
            for (int nf = 0; nf < 2; nf++) {
                #pragma unroll
                for (int e = 0; e < 4; e++) bc[mf][nf][e] = bn[mf][nf][e];
            }
        #pragma unroll
        for (int nf = 0; nf < 2; nf++) { mc[nf][0] = mn2[nf][0]; mc[nf][1] = mn2[nf][1]; }
    }

    #pragma unroll
    for (int mf = 0; mf < 2; mf++) {
        float s0 = rs[mf][0], s1 = rs[mf][1];
        s0 += __shfl_xor_sync(0xffffffffu, s0, 1);
        s0 += __shfl_xor_sync(0xffffffffu, s0, 2);
        s1 += __shfl_xor_sync(0xffffffffu, s1, 1);
        s1 += __shfl_xor_sync(0xffffffffu, s1, 2);
        float inv0 = 1.0f / s0, inv1 = 1.0f / s1;
        int m = wm0 + mf*16 + tq;
        bool st0 = (m < NTOK), st1 = (m + 8 < NTOK);
        size_t r0 = (size_t)(win*NTOK + m)*DIM;
        size_t r1 = r0 + 8*DIM;
        #pragma unroll
        for (int nf4 = 0; nf4 < 4; nf4++) {
            int col = h*DHD + nf4*8 + tr;
            float v0 = oacc[mf][nf4][0]*inv0, v1 = oacc[mf][nf4][1]*inv0;
            float v2 = oacc[mf][nf4][2]*inv1, v3 = oacc[mf][nf4][3]*inv1;
            uint32_t hp0 = cvt_bf2(v0, v1);
            uint32_t lp0 = cvt_bf2(v0 - bf_lo(hp0), v1 - bf_hi(hp0));
            uint32_t hp1 = cvt_bf2(v2, v3);
            uint32_t lp1 = cvt_bf2(v2 - bf_lo(hp1), v3 - bf_hi(hp1));
            if (st0) {
                *(uint32_t*)(aoh + r0 + col) = hp0;
                *(uint32_t*)(aol + r0 + col) = lp0;
            }
            if (st1) {
                *(uint32_t*)(aoh + r1 + col) = hp1;
                *(uint32_t*)(aol + r1 + col) = lp1;
            }
        }
    }
}

// ---------------- launch --------------------------------------------------------
extern "C" void kernel_launch(void* const* d_in, const int* in_sizes, int n_in,
                              void* d_out, int out_size) {
    const float* x          = (const float*)d_in[0];
    const int*   mask       = (const int*)  d_in[1];
    const float* w_qkv      = (const float*)d_in[2];
    const float* w_out      = (const float*)d_in[3];
    const float* bias_table = (const float*)d_in[4];
    const int*   rel_index  = (const int*)  d_in[5];
    float* out = (float*)d_out;

    float *bT;
    cudaGetSymbolAddress((void**)&bT, g_biasT);
    __nv_bfloat16 *ah, *al, *qh, *ql, *kh, *kl, *vh, *vl, *aoh, *aol;
    __nv_bfloat16 *bhq, *blq, *bho, *blo;
    cudaGetSymbolAddress((void**)&ah,  g_ah);
    cudaGetSymbolAddress((void**)&al,  g_al);
    cudaGetSymbolAddress((void**)&qh,  g_qh);
    cudaGetSymbolAddress((void**)&ql,  g_ql);
    cudaGetSymbolAddress((void**)&kh,  g_kh2);
    cudaGetSymbolAddress((void**)&kl,  g_kl2);
    cudaGetSymbolAddress((void**)&vh,  g_vh);
    cudaGetSymbolAddress((void**)&vl,  g_vl);
    cudaGetSymbolAddress((void**)&aoh, g_aoh);
    cudaGetSymbolAddress((void**)&aol, g_aol);
    cudaGetSymbolAddress((void**)&bhq, g_bhq);
    cudaGetSymbolAddress((void**)&blq, g_blq);
    cudaGetSymbolAddress((void**)&bho, g_bho);
    cudaGetSymbolAddress((void**)&blo, g_blo);

    cudaFuncSetAttribute(attn_mma_kernel,
                         cudaFuncAttributeMaxDynamicSharedMemorySize, A_SMEM);
    cudaFuncSetAttribute(qkv_mma_kernel,
                         cudaFuncAttributeMaxDynamicSharedMemorySize, G_SMEM);
    cudaFuncSetAttribute(proj_mma_kernel,
                         cudaFuncAttributeMaxDynamicSharedMemorySize, G_SMEM);

    // side stream + events created on first (uncaptured) call; reused for capture
    static cudaStream_t s1 = [](){ cudaStream_t s; cudaStreamCreateWithFlags(&s, cudaStreamNonBlocking); return s; }();
    static cudaEvent_t e1 = [](){ cudaEvent_t e; cudaEventCreateWithFlags(&e, cudaEventDisableTiming); return e; }();
    static cudaEvent_t e2 = [](){ cudaEvent_t e; cudaEventCreateWithFlags(&e, cudaEventDisableTiming); return e; }();
    static cudaEvent_t e3 = [](){ cudaEvent_t e; cudaEventCreateWithFlags(&e, cudaEventDisableTiming); return e; }();
    static cudaEvent_t e4 = [](){ cudaEvent_t e; cudaEventCreateWithFlags(&e, cudaEventDisableTiming); return e; }();

    prep_kernel<<<PREP_TOT, 256>>>(x, w_qkv, w_out, rel_index, bias_table,
                                   ah, al, bhq, blq, bho, blo, bT);
    // qkv half 0 (windows 0..127 == m-tiles 0..293)
    qkv_mma_kernel<<<dim3(6, 294), 256, G_SMEM>>>(ah, al, bhq, blq,
                                                  qh, ql, kh, kl, vh, vl, 0);
    cudaEventRecord(e1, 0);
    // qkv half 1 overlaps attention half 0
    qkv_mma_kernel<<<dim3(6, 294), 256, G_SMEM>>>(ah, al, bhq, blq,
                                                  qh, ql, kh, kl, vh, vl, 294);
    cudaEventRecord(e2, 0);

    cudaStreamWaitEvent(s1, e1, 0);
    attn_mma_kernel<<<NHEAD*128, 320, A_SMEM, s1>>>(qh, ql, kh, kl, vh, vl,
                                                    mask, bT, aoh, aol, 0);
    cudaEventRecord(e3, s1);
    cudaStreamWaitEvent(s1, e2, 0);
    attn_mma_kernel<<<NHEAD*128, 320, A_SMEM, s1>>>(qh, ql, kh, kl, vh, vl,
                                                    mask, bT, aoh, aol, 128);
    cudaEventRecord(e4, s1);

    // proj half 0 overlaps attention half 1
    cudaStreamWaitEvent(0, e3, 0);
    proj_mma_kernel<<<dim3(2, 294), 256, G_SMEM>>>(aoh, aol, bho, blo, out, 0);
    cudaStreamWaitEvent(0, e4, 0);
    proj_mma_kernel<<<dim3(2, 294), 256, G_SMEM>>>(aoh, aol, bho, blo, out, 294);
}

// round 16
// speedup vs baseline: 1.5179x; 1.5179x over previous
#include <cuda_runtime.h>
#include <cuda_bf16.h>
#include <math.h>
#include <stdint.h>

#define NWIN 256
#define NTOK 294
#define NHEAD 8
#define DHD 32
#define DIM 256
#define MROWS (NWIN*NTOK)        // 75264
#define NPAIR (NTOK*NTOK)        // 86436
#define QSCALE 0.17677669529663687f  // 32^-0.5

// ---------------- scratch ----------------------------------------------------
__device__ float g_biasT[(size_t)NHEAD*NPAIR];
__device__ __nv_bfloat16 g_ah[(size_t)MROWS*DIM];
__device__ __nv_bfloat16 g_al[(size_t)MROWS*DIM];
__device__ __nv_bfloat16 g_qh[(size_t)MROWS*DIM];
__device__ __nv_bfloat16 g_ql[(size_t)MROWS*DIM];
__device__ __nv_bfloat16 g_kh2[(size_t)MROWS*DIM];
__device__ __nv_bfloat16 g_kl2[(size_t)MROWS*DIM];
__device__ __nv_bfloat16 g_vh[(size_t)MROWS*DIM];
__device__ __nv_bfloat16 g_vl[(size_t)MROWS*DIM];
__device__ __nv_bfloat16 g_aoh[(size_t)MROWS*DIM];
__device__ __nv_bfloat16 g_aol[(size_t)MROWS*DIM];
__device__ __nv_bfloat16 g_bhq[768*256];
__device__ __nv_bfloat16 g_blq[768*256];
__device__ __nv_bfloat16 g_bho[256*256];
__device__ __nv_bfloat16 g_blo[256*256];

// ---------------- helpers -----------------------------------------------------
__device__ __forceinline__ uint32_t smem_u32(const void* p) {
    return (uint32_t)__cvta_generic_to_shared(p);
}
__device__ __forceinline__ void ldsm_x4(uint32_t& r0, uint32_t& r1,
                                        uint32_t& r2, uint32_t& r3, uint32_t a) {
    asm volatile("ldmatrix.sync.aligned.m8n8.x4.shared.b16 {%0,%1,%2,%3}, [%4];"
                 : "=r"(r0), "=r"(r1), "=r"(r2), "=r"(r3) : "r"(a));
}
__device__ __forceinline__ void mma_bf16(float* c, uint32_t a0, uint32_t a1,
                                         uint32_t a2, uint32_t a3,
                                         uint32_t b0, uint32_t b1) {
    asm volatile(
        "mma.sync.aligned.m16n8k16.row.col.f32.bf16.bf16.f32 "
        "{%0,%1,%2,%3}, {%4,%5,%6,%7}, {%8,%9}, {%0,%1,%2,%3};"
        : "+f"(c[0]), "+f"(c[1]), "+f"(c[2]), "+f"(c[3])
        : "r"(a0), "r"(a1), "r"(a2), "r"(a3), "r"(b0), "r"(b1));
}
__device__ __forceinline__ uint32_t cvt_bf2(float a, float b) {
    uint32_t r;
    asm("cvt.rn.bf16x2.f32 %0, %1, %2;" : "=r"(r) : "f"(b), "f"(a));
    return r;
}
__device__ __forceinline__ float bf_lo(uint32_t r) { return __uint_as_float(r << 16); }
__device__ __forceinline__ float bf_hi(uint32_t r) { return __uint_as_float(r & 0xffff0000u); }
__device__ __forceinline__ void cpa16(uint32_t s, const void* g) {
    asm volatile("cp.async.cg.shared.global [%0], [%1], 16;" :: "r"(s), "l"(g));
}
#define CPA_COMMIT() asm volatile("cp.async.commit_group;" ::: "memory")
#define CPA_WAIT0()  asm volatile("cp.async.wait_group 0;" ::: "memory")
#define CPA_WAIT1()  asm volatile("cp.async.wait_group 1;" ::: "memory")

// swizzled 16B-chunk offset inside a [rows][4 chunks] (64B-row) tile.
__device__ __forceinline__ uint32_t sw_off(int r, int c) {
    return (uint32_t)(r*64 + ((c ^ ((r >> 1) & 3)) << 4));
}
// Vt tile: 32 rows x 640B (40 chunks of 16B), conflict-free xor swizzle
__device__ __forceinline__ uint32_t vt_off(int d, int c) {
    return (uint32_t)(d*640 + ((((c) & ~7) | (((c) & 7) ^ (d & 7))) << 4));
}
// fp32 epilogue tile: 128 rows x 512B; 8B-unit xor swizzle (conflict-free)
__device__ __forceinline__ uint32_t ep32_off(int r, int cw) {
    return (uint32_t)(r*512 + ((cw ^ ((r & 7) << 2)) << 3));
}

// GEMM row (window-major) -> x/out row (l-major)
__device__ __forceinline__ int map_row(int r) {
    int win = r / NTOK;
    int tok = r - win*NTOK;
    int l   = tok / 49;
    int ww  = tok - l*49;
    return l*12544 + win*49 + ww;
}

// ---------------- merged prelude kernel -----------------------------------------
#define PREP_XS 9408
#define PREP_WQ (PREP_XS + 768)
#define PREP_WO (PREP_WQ + 256)
#define PREP_TOT (PREP_WO + 338)

__global__ void prep_kernel(const float* __restrict__ X,
                            const float* __restrict__ WQ,
                            const float* __restrict__ WO,
                            const int* __restrict__ rel,
                            const float* __restrict__ table,
                            __nv_bfloat16* __restrict__ AH,
                            __nv_bfloat16* __restrict__ AL,
                            __nv_bfloat16* __restrict__ BHQ,
                            __nv_bfloat16* __restrict__ BLQ,
                            __nv_bfloat16* __restrict__ BHO,
                            __nv_bfloat16* __restrict__ BLO,
                            float* __restrict__ biasT) {
    int b = blockIdx.x;
    int tid = threadIdx.x;
    if (b < PREP_XS) {
        int i = b*256 + tid;
        int r = i >> 5, c8 = i & 31;
        const float* src = X + (size_t)map_row(r)*DIM + c8*8;
        float4 f0 = *(const float4*)src;
        float4 f1 = *(const float4*)(src + 4);
        float buf[8] = {f0.x, f0.y, f0.z, f0.w, f1.x, f1.y, f1.z, f1.w};
        __nv_bfloat16 h[8], l[8];
        #pragma unroll
        for (int e = 0; e < 8; e++) {
            __nv_bfloat16 hi = __float2bfloat16(buf[e]);
            h[e] = hi;
            l[e] = __float2bfloat16(buf[e] - __bfloat162float(hi));
        }
        *(uint4*)(AH + (size_t)r*DIM + c8*8) = *(uint4*)h;
        *(uint4*)(AL + (size_t)r*DIM + c8*8) = *(uint4*)l;
    } else if (b < PREP_WQ) {
        int i = (b - PREP_XS)*256 + tid;
        int n = i >> 8, k = i & 255;
        float x = WQ[(size_t)k*768 + n];
        if (n < 256) x *= QSCALE;                  // fold q-scale into weights
        __nv_bfloat16 hi = __float2bfloat16(x);
        BHQ[(size_t)n*256 + k] = hi;
        BLQ[(size_t)n*256 + k] = __float2bfloat16(x - __bfloat162float(hi));
    } else if (b < PREP_WO) {
        int i = (b - PREP_WQ)*256 + tid;
        int n = i >> 8, k = i & 255;
        float x = WO[(size_t)k*256 + n];
        __nv_bfloat16 hi = __float2bfloat16(x);
        BHO[(size_t)n*256 + k] = hi;
        BLO[(size_t)n*256 + k] = __float2bfloat16(x - __bfloat162float(hi));
    } else {
        int t = (b - PREP_WO)*256 + tid;
        if (t >= NPAIR) return;
        int j = t / NTOK, i = t - j*NTOK;
        int idx = rel[i*NTOK + j];
        #pragma unroll
        for (int h = 0; h < NHEAD; h++)
            biasT[(size_t)h*NPAIR + t] = table[idx*NHEAD + h];
    }
}

// ---------------- 3-stage cp.async mma.sync GEMM --------------------------------
#define G_STAGE 32768
#define G_SMEM  (3*G_STAGE)
#define EP_STRIDE 272   /* bf16 epilogue row stride */

template<bool QKV>
__device__ __forceinline__ void gemm2_body(
        const __nv_bfloat16* __restrict__ AHg, const __nv_bfloat16* __restrict__ ALg,
        const __nv_bfloat16* __restrict__ BHg, const __nv_bfloat16* __restrict__ BLg,
        __nv_bfloat16* QH, __nv_bfloat16* QL,
        __nv_bfloat16* KH, __nv_bfloat16* KL,
        __nv_bfloat16* VH, __nv_bfloat16* VL,
        float* __restrict__ OUT) {
    extern __shared__ __align__(16) uint8_t dsm[];
    uint32_t sb = smem_u32(dsm);
    int tid  = threadIdx.x;
    int lane = tid & 31;
    int wid  = tid >> 5;
    int wm   = wid & 1;
    int wn   = wid >> 1;
    int m0 = blockIdx.y * 128;
    int n0 = blockIdx.x * 128;

    int r0 = tid >> 2, c0 = tid & 3;
    const __nv_bfloat16* gAH0 = AHg + (size_t)(m0 + r0)*256      + c0*8;
    const __nv_bfloat16* gAH1 = AHg + (size_t)(m0 + r0 + 64)*256 + c0*8;
    const __nv_bfloat16* gAL0 = ALg + (size_t)(m0 + r0)*256      + c0*8;
    const __nv_bfloat16* gAL1 = ALg + (size_t)(m0 + r0 + 64)*256 + c0*8;
    const __nv_bfloat16* gBH0 = BHg + (size_t)(n0 + r0)*256      + c0*8;
    const __nv_bfloat16* gBH1 = BHg + (size_t)(n0 + r0 + 64)*256 + c0*8;
    const __nv_bfloat16* gBL0 = BLg + (size_t)(n0 + r0)*256      + c0*8;
    const __nv_bfloat16* gBL1 = BLg + (size_t)(n0 + r0 + 64)*256 + c0*8;
    uint32_t oA0 = sw_off(r0, c0), oA1 = sw_off(r0 + 64, c0);

#define STAGE_LOAD(ST, KT) do {                                   \
        uint32_t _b = sb + (ST)*G_STAGE;                          \
        cpa16(_b + 0     + oA0, gAH0 + (KT));                     \
        cpa16(_b + 0     + oA1, gAH1 + (KT));                     \
        cpa16(_b + 8192  + oA0, gAL0 + (KT));                     \
        cpa16(_b + 8192  + oA1, gAL1 + (KT));                     \
        cpa16(_b + 16384 + oA0, gBH0 + (KT));                     \
        cpa16(_b + 16384 + oA1, gBH1 + (KT));                     \
        cpa16(_b + 24576 + oA0, gBL0 + (KT));                     \
        cpa16(_b + 24576 + oA1, gBL1 + (KT));                     \
        CPA_COMMIT();                                             \
    } while (0)

    int a_row = ((lane >> 3) & 1)*8 + (lane & 7);
    int a_ch  = lane >> 4;
    int b_row = (lane >> 4)*8 + (lane & 7);
    int b_ch  = (lane >> 3) & 1;

    float acc[4][4][4];
    #pragma unroll
    for (int i = 0; i < 4; i++)
        #pragma unroll
        for (int j = 0; j < 4; j++)
            #pragma unroll
            for (int e = 0; e < 4; e++) acc[i][j][e] = 0.f;

    STAGE_LOAD(0, 0);
    STAGE_LOAD(1, 32);

    #pragma unroll
    for (int kt8 = 0; kt8 < 8; kt8++) {
        if (kt8 < 7) CPA_WAIT1(); else CPA_WAIT0();
        __syncthreads();
        if (kt8 + 2 < 8) STAGE_LOAD((kt8 + 2) % 3, (kt8 + 2)*32);

        uint32_t ah_b = sb + (kt8 % 3)*G_STAGE;
        uint32_t al_b = ah_b + 8192;
        uint32_t bh_b = ah_b + 16384;
        uint32_t bl_b = ah_b + 24576;

        #pragma unroll
        for (int s = 0; s < 2; s++) {
            uint32_t ah[16], al[16], bh[8], bl[8];
            #pragma unroll
            for (int mf = 0; mf < 4; mf++) {
                uint32_t off = sw_off(wm*64 + mf*16 + a_row, s*2 + a_ch);
                ldsm_x4(ah[4*mf], ah[4*mf+1], ah[4*mf+2], ah[4*mf+3], ah_b + off);
                ldsm_x4(al[4*mf], al[4*mf+1], al[4*mf+2], al[4*mf+3], al_b + off);
            }
            #pragma unroll
            for (int np = 0; np < 2; np++) {
                uint32_t off = sw_off(wn*32 + np*16 + b_row, s*2 + b_ch);
                ldsm_x4(bh[4*np], bh[4*np+1], bh[4*np+2], bh[4*np+3], bh_b + off);
                ldsm_x4(bl[4*np], bl[4*np+1], bl[4*np+2], bl[4*np+3], bl_b + off);
            }
            #pragma unroll
            for (int mf = 0; mf < 4; mf++)
                #pragma unroll
                for (int nf = 0; nf < 4; nf++) {
                    mma_bf16(acc[mf][nf], ah[4*mf], ah[4*mf+1], ah[4*mf+2], ah[4*mf+3],
                             bh[2*nf], bh[2*nf+1]);
                    mma_bf16(acc[mf][nf], ah[4*mf], ah[4*mf+1], ah[4*mf+2], ah[4*mf+3],
                             bl[2*nf], bl[2*nf+1]);
                    mma_bf16(acc[mf][nf], al[4*mf], al[4*mf+1], al[4*mf+2], al[4*mf+3],
                             bh[2*nf], bh[2*nf+1]);
                }
        }
    }

    int tq = lane >> 2;
    int tr = (lane & 3)*2;
    if (QKV) {
        int sel = n0 >> 8;
        int cc0 = n0 & 255;
        __nv_bfloat16* dh = (sel == 0) ? QH : (sel == 1) ? KH : VH;
        __nv_bfloat16* dl = (sel == 0) ? QL : (sel == 1) ? KL : VL;
        #pragma unroll
        for (int pl = 0; pl < 2; pl++) {
            __syncthreads();
            #pragma unroll
            for (int mf = 0; mf < 4; mf++)
                #pragma unroll
                for (int nf = 0; nf < 4; nf++) {
                    int r = wm*64 + mf*16 + tq;
                    int cb = (wn*32 + nf*8 + tr)*2;
                    float v0 = acc[mf][nf][0], v1 = acc[mf][nf][1];
                    float v2 = acc[mf][nf][2], v3 = acc[mf][nf][3];
                    uint32_t h0 = cvt_bf2(v0, v1);
                    uint32_t h1 = cvt_bf2(v2, v3);
                    uint32_t w0, w1;
                    if (pl == 0) { w0 = h0; w1 = h1; }
                    else {
                        w0 = cvt_bf2(v0 - bf_lo(h0), v1 - bf_hi(h0));
                        w1 = cvt_bf2(v2 - bf_lo(h1), v3 - bf_hi(h1));
                    }
                    *(uint32_t*)(dsm + r*EP_STRIDE + cb)       = w0;
                    *(uint32_t*)(dsm + (r + 8)*EP_STRIDE + cb) = w1;
                }
            __syncthreads();
            __nv_bfloat16* dst = (pl == 0) ? dh : dl;
            #pragma unroll
            for (int k2 = 0; k2 < 8; k2++) {
                int idx = tid + k2*256;
                int r = idx >> 4, ch = idx & 15;
                uint4 val = *(uint4*)(dsm + r*EP_STRIDE + ch*16);
                *(uint4*)(dst + (size_t)(m0 + r)*256 + cc0 + ch*8) = val;
            }
        }
    } else {
        __syncthreads();
        #pragma unroll
        for (int mf = 0; mf < 4; mf++)
            #pragma unroll
            for (int nf = 0; nf < 4; nf++) {
                int r = wm*64 + mf*16 + tq;
                int cw = (wn*32 + nf*8 + tr) >> 1;
                float2 v0 = {acc[mf][nf][0], acc[mf][nf][1]};
                float2 v1 = {acc[mf][nf][2], acc[mf][nf][3]};
                *(float2*)(dsm + ep32_off(r, cw))     = v0;
                *(float2*)(dsm + ep32_off(r + 8, cw)) = v1;
            }
        __syncthreads();
        #pragma unroll
        for (int k2 = 0; k2 < 16; k2++) {
            int idx = tid + k2*256;
            int r = idx >> 5, ch = idx & 31;
            uint4 val = *(uint4*)(dsm + ep32_off(r, 2*ch));
            int g = map_row(m0 + r);
            *(uint4*)(OUT + (size_t)g*256 + n0 + ch*4) = val;
        }
    }
#undef STAGE_LOAD
}

__global__ __launch_bounds__(256, 2) void qkv_mma_kernel(
        const __nv_bfloat16* __restrict__ AH, const __nv_bfloat16* __restrict__ AL,
        const __nv_bfloat16* __restrict__ BH, const __nv_bfloat16* __restrict__ BL,
        __nv_bfloat16* QH, __nv_bfloat16* QL, __nv_bfloat16* KH, __nv_bfloat16* KL,
        __nv_bfloat16* VH, __nv_bfloat16* VL) {
    gemm2_body<true>(AH, AL, BH, BL, QH, QL, KH, KL, VH, VL, nullptr);
}

__global__ __launch_bounds__(256, 2) void proj_mma_kernel(
        const __nv_bfloat16* __restrict__ AH, const __nv_bfloat16* __restrict__ AL,
        const __nv_bfloat16* __restrict__ BH, const __nv_bfloat16* __restrict__ BL,
        float* __restrict__ OUT) {
    gemm2_body<false>(AH, AL, BH, BL,
                      nullptr, nullptr, nullptr, nullptr, nullptr, nullptr, OUT);
}

// ---------------- attention via mma.sync + cp.async staging ----------------------
#define MPAD 320
#define A_QH 0
#define A_QL 20480
#define A_KH 40960
#define A_KL 60416
#define A_VTH 79872
#define A_VTL 100352
#define A_MSKF 120832
#define A_KLIST 122048
#define A_MSRAW 123264
#define A_PCNT 124448
#define A_SMEM 124464

__global__ __launch_bounds__(320, 1) void attn_mma_kernel(
        const __nv_bfloat16* __restrict__ gqh, const __nv_bfloat16* __restrict__ gql,
        const __nv_bfloat16* __restrict__ gkh, const __nv_bfloat16* __restrict__ gkl,
        const __nv_bfloat16* __restrict__ gvh, const __nv_bfloat16* __restrict__ gvl,
        const int* __restrict__ mask, const float* __restrict__ biasT,
        __nv_bfloat16* __restrict__ aoh, __nv_bfloat16* __restrict__ aol) {
    extern __shared__ __align__(16) uint8_t sm8[];
    float* mskf = (float*)(sm8 + A_MSKF);
    int*   kls  = (int*)(sm8 + A_KLIST);
    int*   msr  = (int*)(sm8 + A_MSRAW);
    int*   pcnt = (int*)(sm8 + A_PCNT);

    int tid = threadIdx.x, lane = tid & 31, wid = tid >> 5;
    // head-major ordering: concurrent CTAs share one head's bias slice in L2
    int h   = blockIdx.x >> 8;
    int win = blockIdx.x & 255;
    size_t base = ((size_t)win*NTOK)*DIM + h*DHD;
    uint32_t sb = smem_u32(sm8);

    for (int idx = tid; idx < NTOK*4; idx += 320) {
        int r = idx >> 2, c = idx & 3;
        size_t src = base + (size_t)r*DIM + c*8;
        uint32_t off = sw_off(r, c);
        cpa16(sb + A_QH + off, gqh + src);
        cpa16(sb + A_QL + off, gql + src);
    }
    for (int t = tid; t < NTOK; t += 320) {
        int l = t / 49, ww = t - l*49;
        msr[t] = mask[(win*49 + ww)*6 + l];
    }
    for (int t = tid; t < 304; t += 320) { kls[t] = 293; mskf[t] = 0.f; }
    for (int idx = NTOK*4 + tid; idx < MPAD*4; idx += 320) {
        int r = idx >> 2, c = idx & 3;
        uint4 z = {0, 0, 0, 0};
        uint32_t off = sw_off(r, c);
        *(uint4*)(sm8 + A_QH + off) = z;
        *(uint4*)(sm8 + A_QL + off) = z;
    }
    __syncthreads();

    if (tid < 32) {
        int c = 0;
        for (int b0 = 0; b0 < NTOK; b0 += 32) {
            int j = b0 + lane;
            int mj = (j < NTOK) ? msr[j] : 0;
            unsigned bal = __ballot_sync(0xffffffffu, mj != 0);
            if (mj) {
                int pos = c + __popc(bal & ((1u << lane) - 1));
                kls[pos] = j;
                mskf[pos] = 1.f;
            }
            c += __popc(bal);
        }
        if (lane == 0) pcnt[0] = c;
    }
    __syncthreads();
    int cnt  = pcnt[0];
    int nch  = (cnt + 15) >> 4;
    int cntp = nch << 4;

    for (int idx = tid; idx < cntp*4; idx += 320) {
        int jj = idx >> 2, c = idx & 3;
        int j = kls[jj];
        size_t src = base + (size_t)j*DIM + c*8;
        uint32_t off = sw_off(jj, c);
        cpa16(sb + A_KH + off, gkh + src);
        cpa16(sb + A_KL + off, gkl + src);
    }
    for (int idx = tid; idx < cntp*4; idx += 320) {
        int jp = idx >> 3, d4 = idx & 7;
        int jj0 = jp*2;
        int j0 = kls[jj0], j1 = kls[jj0 + 1];
        size_t s0 = base + (size_t)j0*DIM + d4*4;
        size_t s1 = base + (size_t)j1*DIM + d4*4;
        uint2 wh0 = *(const uint2*)(gvh + s0);
        uint2 wh1 = *(const uint2*)(gvh + s1);
        uint2 wl0 = *(const uint2*)(gvl + s0);
        uint2 wl1 = *(const uint2*)(gvl + s1);
        int cb = jj0 >> 3;
        int ib = (jj0 & 7)*2;
        int d = d4*4;
        *(uint32_t*)(sm8 + A_VTH + vt_off(d+0, cb) + ib) = __byte_perm(wh0.x, wh1.x, 0x5410);
        *(uint32_t*)(sm8 + A_VTH + vt_off(d+1, cb) + ib) = __byte_perm(wh0.x, wh1.x, 0x7632);
        *(uint32_t*)(sm8 + A_VTH + vt_off(d+2, cb) + ib) = __byte_perm(wh0.y, wh1.y, 0x5410);
        *(uint32_t*)(sm8 + A_VTH + vt_off(d+3, cb) + ib) = __byte_perm(wh0.y, wh1.y, 0x7632);
        *(uint32_t*)(sm8 + A_VTL + vt_off(d+0, cb) + ib) = __byte_perm(wl0.x, wl1.x, 0x5410);
        *(uint32_t*)(sm8 + A_VTL + vt_off(d+1, cb) + ib) = __byte_perm(wl0.x, wl1.x, 0x7632);
        *(uint32_t*)(sm8 + A_VTL + vt_off(d+2, cb) + ib) = __byte_perm(wl0.y, wl1.y, 0x5410);
        *(uint32_t*)(sm8 + A_VTL + vt_off(d+3, cb) + ib) = __byte_perm(wl0.y, wl1.y, 0x7632);
    }
    CPA_COMMIT();
    CPA_WAIT0();
    __syncthreads();

    int tq = lane >> 2;
    int tr = (lane & 3)*2;
    int a_row = ((lane >> 3) & 1)*8 + (lane & 7);
    int a_ch  = lane >> 4;
    int b_row = (lane >> 4)*8 + (lane & 7);
    int b_ch  = (lane >> 3) & 1;
    int wm0 = wid*32;

    uint32_t qh[2][2][4], ql[2][2][4];
    #pragma unroll
    for (int mf = 0; mf < 2; mf++)
        #pragma unroll
        for (int s = 0; s < 2; s++) {
            uint32_t off = sw_off(wm0 + mf*16 + a_row, s*2 + a_ch);
            ldsm_x4(qh[mf][s][0], qh[mf][s][1], qh[mf][s][2], qh[mf][s][3], sb + A_QH + off);
            ldsm_x4(ql[mf][s][0], ql[mf][s][1], ql[mf][s][2], ql[mf][s][3], sb + A_QL + off);
        }

    int i0a[2], i1a[2];
    #pragma unroll
    for (int mf = 0; mf < 2; mf++) {
        int b0 = wm0 + mf*16 + tq;
        i0a[mf] = (b0 < 293) ? b0 : 293;
        int b1 = b0 + 8;
        i1a[mf] = (b1 < 293) ? b1 : 293;
    }
    const float* bp = biasT + (size_t)h*NPAIR;

    float oacc[2][4][4];
    #pragma unroll
    for (int mf = 0; mf < 2; mf++)
        #pragma unroll
        for (int nf = 0; nf < 4; nf++)
            #pragma unroll
            for (int e = 0; e < 4; e++) oacc[mf][nf][e] = 0.f;
    float rs[2][2] = {{0.f, 0.f}, {0.f, 0.f}};

    float bc[2][2][4], mc[2][2];
#define LOAD_BIAS(CH, B, M) do {                                            \
        int _kb = (CH)*16;                                                  \
        _Pragma("unroll")                                                   \
        for (int _nf = 0; _nf < 2; _nf++) {                                 \
            int2 _j2 = *(const int2*)(kls + _kb + _nf*8 + tr);              \
            float2 _m2 = *(const float2*)(mskf + _kb + _nf*8 + tr);         \
            (M)[_nf][0] = _m2.x; (M)[_nf][1] = _m2.y;                       \
            const float* _ba = bp + (size_t)_j2.x*NTOK;                     \
            const float* _bb = bp + (size_t)_j2.y*NTOK;                     \
            _Pragma("unroll")                                               \
            for (int _mf = 0; _mf < 2; _mf++) {                             \
                (B)[_mf][_nf][0] = __ldg(_ba + i0a[_mf]);                   \
                (B)[_mf][_nf][1] = __ldg(_bb + i0a[_mf]);                   \
                (B)[_mf][_nf][2] = __ldg(_ba + i1a[_mf]);                   \
                (B)[_mf][_nf][3] = __ldg(_bb + i1a[_mf]);                   \
            }                                                               \
        } } while (0)

    LOAD_BIAS(0, bc, mc);

    for (int ch = 0; ch < nch; ch++) {
        int kb = ch*16;
        uint32_t kh[8], kl2[8], vh[8], vl[8];
        {
            uint32_t o0 = sw_off(kb + b_row, b_ch);
            uint32_t o1 = sw_off(kb + b_row, 2 + b_ch);
            ldsm_x4(kh[0], kh[1], kh[2], kh[3], sb + A_KH + o0);
            ldsm_x4(kh[4], kh[5], kh[6], kh[7], sb + A_KH + o1);
            ldsm_x4(kl2[0], kl2[1], kl2[2], kl2[3], sb + A_KL + o0);
            ldsm_x4(kl2[4], kl2[5], kl2[6], kl2[7], sb + A_KL + o1);
            uint32_t v0o = vt_off(b_row, ch*2 + b_ch);
            uint32_t v1o = vt_off(16 + b_row, ch*2 + b_ch);
            ldsm_x4(vh[0], vh[1], vh[2], vh[3], sb + A_VTH + v0o);
            ldsm_x4(vh[4], vh[5], vh[6], vh[7], sb + A_VTH + v1o);
            ldsm_x4(vl[0], vl[1], vl[2], vl[3], sb + A_VTL + v0o);
            ldsm_x4(vl[4], vl[5], vl[6], vl[7], sb + A_VTL + v1o);
        }

        float bn[2][2][4], mn2[2][2];
        if (ch + 1 < nch) LOAD_BIAS(ch + 1, bn, mn2);

        float sacc[2][2][4];
        #pragma unroll
        for (int mf = 0; mf < 2; mf++)
            #pragma unroll
            for (int nf = 0; nf < 2; nf++)
                #pragma unroll
                for (int e = 0; e < 4; e++) sacc[mf][nf][e] = 0.f;

        #pragma unroll
        for (int mf = 0; mf < 2; mf++)
            #pragma unroll
            for (int s = 0; s < 2; s++) {
                mma_bf16(sacc[mf][0], qh[mf][s][0], qh[mf][s][1], qh[mf][s][2], qh[mf][s][3],
                         kh[4*s], kh[4*s+1]);
                mma_bf16(sacc[mf][1], qh[mf][s][0], qh[mf][s][1], qh[mf][s][2], qh[mf][s][3],
                         kh[4*s+2], kh[4*s+3]);
                mma_bf16(sacc[mf][0], qh[mf][s][0], qh[mf][s][1], qh[mf][s][2], qh[mf][s][3],
                         kl2[4*s], kl2[4*s+1]);
                mma_bf16(sacc[mf][1], qh[mf][s][0], qh[mf][s][1], qh[mf][s][2], qh[mf][s][3],
                         kl2[4*s+2], kl2[4*s+3]);
                mma_bf16(sacc[mf][0], ql[mf][s][0], ql[mf][s][1], ql[mf][s][2], ql[mf][s][3],
                         kh[4*s], kh[4*s+1]);
                mma_bf16(sacc[mf][1], ql[mf][s][0], ql[mf][s][1], ql[mf][s][2], ql[mf][s][3],
                         kh[4*s+2], kh[4*s+3]);
            }

        uint32_t pah[2][4], pal[2][4];
        #pragma unroll
        for (int mf = 0; mf < 2; mf++)
            #pragma unroll
            for (int nf = 0; nf < 2; nf++) {
                float p0 = __expf(sacc[mf][nf][0] + bc[mf][nf][0]) * mc[nf][0];
                float p1 = __expf(sacc[mf][nf][1] + bc[mf][nf][1]) * mc[nf][1];
                float p2 = __expf(sacc[mf][nf][2] + bc[mf][nf][2]) * mc[nf][0];
                float p3 = __expf(sacc[mf][nf][3] + bc[mf][nf][3]) * mc[nf][1];
                rs[mf][0] += p0 + p1;
                rs[mf][1] += p2 + p3;
                uint32_t hA = cvt_bf2(p0, p1);
                uint32_t hB = cvt_bf2(p2, p3);
                pah[mf][2*nf]   = hA;
                pah[mf][2*nf+1] = hB;
                pal[mf][2*nf]   = cvt_bf2(p0 - bf_lo(hA), p1 - bf_hi(hA));
                pal[mf][2*nf+1] = cvt_bf2(p2 - bf_lo(hB), p3 - bf_hi(hB));
            }

        #pragma unroll
        for (int mf = 0; mf < 2; mf++)
            #pragma unroll
            for (int nf4 = 0; nf4 < 4; nf4++) {
                mma_bf16(oacc[mf][nf4], pah[mf][0], pah[mf][1], pah[mf][2], pah[mf][3],
                         vh[2*nf4], vh[2*nf4+1]);
                mma_bf16(oacc[mf][nf4], pah[mf][0], pah[mf][1], pah[mf][2], pah[mf][3],
                         vl[2*nf4], vl[2*nf4+1]);
                mma_bf16(oacc[mf][nf4], pal[mf][0], pal[mf][1], pal[mf][2], pal[mf][3],
                         vh[2*nf4], vh[2*nf4+1]);
            }

        #pragma unroll
        for (int mf = 0; mf < 2; mf++)
            #pragma unroll
            for (int nf = 0; nf < 2; nf++) {
                #pragma unroll
                for (int e = 0; e < 4; e++) bc[mf][nf][e] = bn[mf][nf][e];
            }
        #pragma unroll
        for (int nf = 0; nf < 2; nf++) { mc[nf][0] = mn2[nf][0]; mc[nf][1] = mn2[nf][1]; }
    }

    #pragma unroll
    for (int mf = 0; mf < 2; mf++) {
        float s0 = rs[mf][0], s1 = rs[mf][1];
        s0 += __shfl_xor_sync(0xffffffffu, s0, 1);
        s0 += __shfl_xor_sync(0xffffffffu, s0, 2);
        s1 += __shfl_xor_sync(0xffffffffu, s1, 1);
        s1 += __shfl_xor_sync(0xffffffffu, s1, 2);
        float inv0 = 1.0f / s0, inv1 = 1.0f / s1;
        int m = wm0 + mf*16 + tq;
        bool st0 = (m < NTOK), st1 = (m + 8 < NTOK);
        size_t r0 = (size_t)(win*NTOK + m)*DIM;
        size_t r1 = r0 + 8*DIM;
        #pragma unroll
        for (int nf4 = 0; nf4 < 4; nf4++) {
            int col = h*DHD + nf4*8 + tr;
            float v0 = oacc[mf][nf4][0]*inv0, v1 = oacc[mf][nf4][1]*inv0;
            float v2 = oacc[mf][nf4][2]*inv1, v3 = oacc[mf][nf4][3]*inv1;
            uint32_t hp0 = cvt_bf2(v0, v1);
            uint32_t lp0 = cvt_bf2(v0 - bf_lo(hp0), v1 - bf_hi(hp0));
            uint32_t hp1 = cvt_bf2(v2, v3);
            uint32_t lp1 = cvt_bf2(v2 - bf_lo(hp1), v3 - bf_hi(hp1));
            if (st0) {
                *(uint32_t*)(aoh + r0 + col) = hp0;
                *(uint32_t*)(aol + r0 + col) = lp0;
            }
            if (st1) {
                *(uint32_t*)(aoh + r1 + col) = hp1;
                *(uint32_t*)(aol + r1 + col) = lp1;
            }
        }
    }
}

// ---------------- launch --------------------------------------------------------
extern "C" void kernel_launch(void* const* d_in, const int* in_sizes, int n_in,
                              void* d_out, int out_size) {
    const float* x          = (const float*)d_in[0];
    const int*   mask       = (const int*)  d_in[1];
    const float* w_qkv      = (const float*)d_in[2];
    const float* w_out      = (const float*)d_in[3];
    const float* bias_table = (const float*)d_in[4];
    const int*   rel_index  = (const int*)  d_in[5];
    float* out = (float*)d_out;

    float *bT;
    cudaGetSymbolAddress((void**)&bT, g_biasT);
    __nv_bfloat16 *ah, *al, *qh, *ql, *kh, *kl, *vh, *vl, *aoh, *aol;
    __nv_bfloat16 *bhq, *blq, *bho, *blo;
    cudaGetSymbolAddress((void**)&ah,  g_ah);
    cudaGetSymbolAddress((void**)&al,  g_al);
    cudaGetSymbolAddress((void**)&qh,  g_qh);
    cudaGetSymbolAddress((void**)&ql,  g_ql);
    cudaGetSymbolAddress((void**)&kh,  g_kh2);
    cudaGetSymbolAddress((void**)&kl,  g_kl2);
    cudaGetSymbolAddress((void**)&vh,  g_vh);
    cudaGetSymbolAddress((void**)&vl,  g_vl);
    cudaGetSymbolAddress((void**)&aoh, g_aoh);
    cudaGetSymbolAddress((void**)&aol, g_aol);
    cudaGetSymbolAddress((void**)&bhq, g_bhq);
    cudaGetSymbolAddress((void**)&blq, g_blq);
    cudaGetSymbolAddress((void**)&bho, g_bho);
    cudaGetSymbolAddress((void**)&blo, g_blo);

    cudaFuncSetAttribute(attn_mma_kernel,
                         cudaFuncAttributeMaxDynamicSharedMemorySize, A_SMEM);
    cudaFuncSetAttribute(qkv_mma_kernel,
                         cudaFuncAttributeMaxDynamicSharedMemorySize, G_SMEM);
    cudaFuncSetAttribute(proj_mma_kernel,
                         cudaFuncAttributeMaxDynamicSharedMemorySize, G_SMEM);

    prep_kernel<<<PREP_TOT, 256>>>(x, w_qkv, w_out, rel_index, bias_table,
                                   ah, al, bhq, blq, bho, blo, bT);
    qkv_mma_kernel<<<dim3(6, MROWS/128), 256, G_SMEM>>>(ah, al, bhq, blq,
                                                        qh, ql, kh, kl, vh, vl);
    attn_mma_kernel<<<NWIN*NHEAD, 320, A_SMEM>>>(qh, ql, kh, kl, vh, vl,
                                                 mask, bT, aoh, aol);
    proj_mma_kernel<<<dim3(2, MROWS/128), 256, G_SMEM>>>(aoh, aol, bho, blo, out);
}